// round 1
// baseline (speedup 1.0000x reference)
#include <cuda_runtime.h>
#include <cstdint>

#define N_NODES 50000
#define N_EDGES 1600000
#define G_GRAPHS 256
#define IN_CH 64
#define EC 32
#define H_CH 64
#define OUT_CH 10

__device__ float g_edge_aggr[N_NODES * EC];
__device__ float g_y[N_NODES * H_CH];
__device__ float g_u[N_NODES * H_CH];
__device__ float g_agg[N_NODES * H_CH];
__device__ float g_x[N_NODES * H_CH];
__device__ float g_pooled[G_GRAPHS * H_CH];

__device__ __forceinline__ void red4(float* addr, float4 v) {
    asm volatile("red.global.add.v4.f32 [%0], {%1,%2,%3,%4};"
                 :: "l"(addr), "f"(v.x), "f"(v.y), "f"(v.z), "f"(v.w)
                 : "memory");
}

__global__ void k_zero(float* __restrict__ p, int n4) {
    int i = blockIdx.x * blockDim.x + threadIdx.x;
    if (i < n4) reinterpret_cast<float4*>(p)[i] = make_float4(0.f, 0.f, 0.f, 0.f);
}

__global__ void k_edge_aggr(const float* __restrict__ edge_attr,
                            const int* __restrict__ edge_index,
                            float* __restrict__ out) {
    int tid = blockIdx.x * blockDim.x + threadIdx.x;
    int e = tid >> 3, p = tid & 7;
    if (e >= N_EDGES) return;
    int r = edge_index[e];
    float4 v = *reinterpret_cast<const float4*>(edge_attr + (size_t)e * EC + p * 4);
    red4(out + (size_t)r * EC + p * 4, v);
}

__global__ void k_edge_gs(const int* __restrict__ edge_index,
                          float* __restrict__ agg) {
    int tid = blockIdx.x * blockDim.x + threadIdx.x;
    int e = tid >> 4, p = tid & 15;
    if (e >= N_EDGES) return;
    int r = edge_index[e];
    int c = edge_index[N_EDGES + e];
    float4 v = *reinterpret_cast<const float4*>(&g_y[(size_t)r * H_CH + p * 4]);
    red4(agg + (size_t)c * H_CH + p * 4, v);
}

__global__ void k_node_mlp1(const float* __restrict__ x_in,
                            const float* __restrict__ W1_rel,
                            const float* __restrict__ W1_root,
                            const float* __restrict__ b1_root) {
    extern __shared__ float sm[];
    float* xs = sm;            // [64][100]
    float* Ws = sm + 6400;     // [96][128]
    float* b1 = Ws + 12288;    // [64]
    const int tid = threadIdx.x;
    const int node0 = blockIdx.x * 64;

    for (int i = tid; i < 96 * 128; i += 256) {
        int k = i >> 7, j = i & 127;
        Ws[i] = (j < 64) ? W1_rel[k * 64 + j] : W1_root[k * 64 + (j - 64)];
    }
    if (tid < 64) b1[tid] = b1_root[tid];
    for (int i = tid; i < 64 * 96; i += 256) {
        int n = i / 96, k = i - n * 96;
        int node = node0 + n;
        float v = 0.f;
        if (node < N_NODES)
            v = (k < 64) ? x_in[(size_t)node * 64 + k]
                         : g_edge_aggr[(size_t)node * EC + (k - 64)];
        xs[n * 100 + k] = v;
    }
    __syncthreads();

    const int og = tid & 15, ng = tid >> 4;
    const int j0 = og * 8;
    float acc[4][8];
#pragma unroll
    for (int i = 0; i < 4; i++)
#pragma unroll
        for (int j = 0; j < 8; j++) acc[i][j] = 0.f;

#pragma unroll 4
    for (int k = 0; k < 96; k++) {
        float4 wA = *reinterpret_cast<const float4*>(&Ws[k * 128 + j0]);
        float4 wB = *reinterpret_cast<const float4*>(&Ws[k * 128 + j0 + 4]);
#pragma unroll
        for (int i = 0; i < 4; i++) {
            float a = xs[(ng + 16 * i) * 100 + k];
            acc[i][0] = fmaf(a, wA.x, acc[i][0]);
            acc[i][1] = fmaf(a, wA.y, acc[i][1]);
            acc[i][2] = fmaf(a, wA.z, acc[i][2]);
            acc[i][3] = fmaf(a, wA.w, acc[i][3]);
            acc[i][4] = fmaf(a, wB.x, acc[i][4]);
            acc[i][5] = fmaf(a, wB.y, acc[i][5]);
            acc[i][6] = fmaf(a, wB.z, acc[i][6]);
            acc[i][7] = fmaf(a, wB.w, acc[i][7]);
        }
    }

#pragma unroll
    for (int i = 0; i < 4; i++) {
        int node = node0 + ng + 16 * i;
        if (node >= N_NODES) continue;
        if (og < 8) {
            float4 o0 = make_float4(acc[i][0], acc[i][1], acc[i][2], acc[i][3]);
            float4 o1 = make_float4(acc[i][4], acc[i][5], acc[i][6], acc[i][7]);
            *reinterpret_cast<float4*>(&g_y[(size_t)node * 64 + j0]) = o0;
            *reinterpret_cast<float4*>(&g_y[(size_t)node * 64 + j0 + 4]) = o1;
        } else {
            int jr = j0 - 64;
            float4 o0 = make_float4(fmaxf(acc[i][0] + b1[jr + 0], 0.f),
                                    fmaxf(acc[i][1] + b1[jr + 1], 0.f),
                                    fmaxf(acc[i][2] + b1[jr + 2], 0.f),
                                    fmaxf(acc[i][3] + b1[jr + 3], 0.f));
            float4 o1 = make_float4(fmaxf(acc[i][4] + b1[jr + 4], 0.f),
                                    fmaxf(acc[i][5] + b1[jr + 5], 0.f),
                                    fmaxf(acc[i][6] + b1[jr + 6], 0.f),
                                    fmaxf(acc[i][7] + b1[jr + 7], 0.f));
            *reinterpret_cast<float4*>(&g_u[(size_t)node * 64 + jr]) = o0;
            *reinterpret_cast<float4*>(&g_u[(size_t)node * 64 + jr + 4]) = o1;
        }
    }
}

__global__ void k_node_mlp2(const float* __restrict__ b1_rel,
                            const float* __restrict__ W2_rel,
                            const float* __restrict__ W2_root,
                            const float* __restrict__ b2_rel,
                            const float* __restrict__ b2_root) {
    extern __shared__ float sm[];
    float* As = sm;            // [64][132]
    float* Ws = sm + 8448;     // [128][64]
    float* b2 = Ws + 8192;     // [64]
    const int tid = threadIdx.x;
    const int node0 = blockIdx.x * 64;

    for (int i = tid; i < 128 * 64; i += 256) {
        int k = i >> 6, j = i & 63;
        Ws[i] = (k < 64) ? W2_rel[k * 64 + j] : W2_root[(k - 64) * 64 + j];
    }
    if (tid < 64) b2[tid] = b2_rel[tid] + b2_root[tid];
    for (int i = tid; i < 64 * 128; i += 256) {
        int n = i >> 7, k = i & 127;
        int node = node0 + n;
        float v = 0.f;
        if (node < N_NODES) {
            if (k < 64) v = fmaxf(g_agg[(size_t)node * 64 + k] + b1_rel[k], 0.f);
            else        v = g_u[(size_t)node * 64 + (k - 64)];
        }
        As[n * 132 + k] = v;
    }
    __syncthreads();

    const int og = tid & 15, ng = tid >> 4;
    const int j0 = og * 4;
    float acc[4][4];
#pragma unroll
    for (int i = 0; i < 4; i++)
#pragma unroll
        for (int j = 0; j < 4; j++) acc[i][j] = 0.f;

#pragma unroll 4
    for (int k = 0; k < 128; k++) {
        float4 w = *reinterpret_cast<const float4*>(&Ws[k * 64 + j0]);
#pragma unroll
        for (int i = 0; i < 4; i++) {
            float a = As[(ng + 16 * i) * 132 + k];
            acc[i][0] = fmaf(a, w.x, acc[i][0]);
            acc[i][1] = fmaf(a, w.y, acc[i][1]);
            acc[i][2] = fmaf(a, w.z, acc[i][2]);
            acc[i][3] = fmaf(a, w.w, acc[i][3]);
        }
    }

#pragma unroll
    for (int i = 0; i < 4; i++) {
        int node = node0 + ng + 16 * i;
        if (node >= N_NODES) continue;
        float4 o = make_float4(fmaxf(acc[i][0] + b2[j0 + 0], 0.f),
                               fmaxf(acc[i][1] + b2[j0 + 1], 0.f),
                               fmaxf(acc[i][2] + b2[j0 + 2], 0.f),
                               fmaxf(acc[i][3] + b2[j0 + 3], 0.f));
        *reinterpret_cast<float4*>(&g_x[(size_t)node * 64 + j0]) = o;
    }
}

__global__ void k_pool(const int* __restrict__ batch) {
    int tid = blockIdx.x * blockDim.x + threadIdx.x;
    int n = tid >> 4, p = tid & 15;
    if (n >= N_NODES) return;
    int b = batch[n];
    float4 v = *reinterpret_cast<const float4*>(&g_x[(size_t)n * 64 + p * 4]);
    red4(&g_pooled[(size_t)b * 64 + p * 4], v);
}

__global__ void k_final(const float* __restrict__ W1, const float* __restrict__ b1,
                        const float* __restrict__ W2, const float* __restrict__ b2,
                        float* __restrict__ out) {
    __shared__ float pr[64];
    __shared__ float h[64];
    int g = blockIdx.x;
    int j = threadIdx.x;
    pr[j] = g_pooled[g * 64 + j];
    __syncthreads();
    float s = b1[j];
#pragma unroll 8
    for (int k = 0; k < 64; k++) s = fmaf(pr[k], W1[k * 64 + j], s);
    h[j] = fmaxf(s, 0.f);
    __syncthreads();
    if (j < OUT_CH) {
        float s2 = b2[j];
#pragma unroll 8
        for (int k = 0; k < 64; k++) s2 = fmaf(h[k], W2[k * OUT_CH + j], s2);
        out[g * OUT_CH + j] = s2;
    }
}

extern "C" void kernel_launch(void* const* d_in, const int* in_sizes, int n_in,
                              void* d_out, int out_size) {
    const float* x         = (const float*)d_in[0];
    const float* edge_attr = (const float*)d_in[1];
    const float* relW1[2]  = {(const float*)d_in[2],  (const float*)d_in[10]};
    const float* relb1[2]  = {(const float*)d_in[3],  (const float*)d_in[11]};
    const float* relW2[2]  = {(const float*)d_in[4],  (const float*)d_in[12]};
    const float* relb2[2]  = {(const float*)d_in[5],  (const float*)d_in[13]};
    const float* rootW1[2] = {(const float*)d_in[6],  (const float*)d_in[14]};
    const float* rootb1[2] = {(const float*)d_in[7],  (const float*)d_in[15]};
    const float* rootW2[2] = {(const float*)d_in[8],  (const float*)d_in[16]};
    const float* rootb2[2] = {(const float*)d_in[9],  (const float*)d_in[17]};
    const float* finW1 = (const float*)d_in[18];
    const float* finb1 = (const float*)d_in[19];
    const float* finW2 = (const float*)d_in[20];
    const float* finb2 = (const float*)d_in[21];
    const int* edge_index = (const int*)d_in[22];
    const int* batch      = (const int*)d_in[23];
    float* out = (float*)d_out;

    float *p_ea, *p_agg, *p_x, *p_pooled;
    cudaGetSymbolAddress((void**)&p_ea, g_edge_aggr);
    cudaGetSymbolAddress((void**)&p_agg, g_agg);
    cudaGetSymbolAddress((void**)&p_x, g_x);
    cudaGetSymbolAddress((void**)&p_pooled, g_pooled);

    const int SMEM1 = (6400 + 12288 + 64) * 4;
    const int SMEM2 = (8448 + 8192 + 64) * 4;
    cudaFuncSetAttribute(k_node_mlp1, cudaFuncAttributeMaxDynamicSharedMemorySize, SMEM1);
    cudaFuncSetAttribute(k_node_mlp2, cudaFuncAttributeMaxDynamicSharedMemorySize, SMEM2);

    const int NODE_BLOCKS = (N_NODES + 63) / 64;

    k_zero<<<(N_NODES * EC / 4 + 255) / 256, 256>>>(p_ea, N_NODES * EC / 4);
    k_edge_aggr<<<(N_EDGES * 8) / 256, 256>>>(edge_attr, edge_index, p_ea);

    for (int l = 0; l < 2; l++) {
        const float* x_in = (l == 0) ? x : p_x;
        k_node_mlp1<<<NODE_BLOCKS, 256, SMEM1>>>(x_in, relW1[l], rootW1[l], rootb1[l]);
        k_zero<<<(N_NODES * H_CH / 4 + 255) / 256, 256>>>(p_agg, N_NODES * H_CH / 4);
        k_edge_gs<<<(N_EDGES * 16) / 256, 256>>>(edge_index, p_agg);
        k_node_mlp2<<<NODE_BLOCKS, 256, SMEM2>>>(relb1[l], relW2[l], rootW2[l], relb2[l], rootb2[l]);
    }

    k_zero<<<(G_GRAPHS * H_CH / 4 + 255) / 256, 256>>>(p_pooled, G_GRAPHS * H_CH / 4);
    k_pool<<<(N_NODES * 16 + 255) / 256, 256>>>(batch);
    k_final<<<G_GRAPHS, 64>>>(finW1, finb1, finW2, finb2, out);
}

// round 2
// speedup vs baseline: 1.1269x; 1.1269x over previous
#include <cuda_runtime.h>
#include <cstdint>

#define N_NODES 50000
#define N_EDGES 1600000
#define G_GRAPHS 256
#define IN_CH 64
#define EC 32
#define H_CH 64
#define OUT_CH 10

// ---------------- scratch ----------------
__device__ float g_edge_aggr[N_NODES * EC];
__device__ float g_y[N_NODES * H_CH];
__device__ float g_u[N_NODES * H_CH];
__device__ float g_agg[N_NODES * H_CH];
__device__ float g_x[N_NODES * H_CH];
__device__ float g_pooled[G_GRAPHS * H_CH];
__device__ int   g_icnt[2 * N_NODES];   // [0..N): hist counts, [N..2N): fill cursors
__device__ int   g_off[N_NODES + 1];
__device__ int   g_csr[N_EDGES];

// ---------------- PTX helpers ----------------
__device__ __forceinline__ void red4(float* addr, float4 v) {
    asm volatile("red.global.add.v4.f32 [%0], {%1,%2,%3,%4};"
                 :: "l"(addr), "f"(v.x), "f"(v.y), "f"(v.z), "f"(v.w)
                 : "memory");
}
__device__ __forceinline__ void ffma2(unsigned long long& d,
                                      unsigned long long a, unsigned long long b) {
    asm("fma.rn.f32x2 %0, %1, %2, %0;" : "+l"(d) : "l"(a), "l"(b));
}
__device__ __forceinline__ unsigned long long bcast2(float a) {
    unsigned long long r;
    asm("mov.b64 %0, {%1, %1};" : "=l"(r) : "f"(a));
    return r;
}
__device__ __forceinline__ float2 u2f(unsigned long long v) {
    float2 f;
    asm("mov.b64 {%0, %1}, %2;" : "=f"(f.x), "=f"(f.y) : "l"(v));
    return f;
}

// ---------------- CSR build ----------------
__global__ void k_hist(const int* __restrict__ edge_index) {
    int e = blockIdx.x * blockDim.x + threadIdx.x;
    if (e >= N_EDGES) return;
    atomicAdd(&g_icnt[edge_index[N_EDGES + e]], 1);
}

__global__ void k_scan() {
    __shared__ int wsum[32];
    __shared__ int chunk_base;
    int tid = threadIdx.x, lane = tid & 31, wid = tid >> 5;
    if (tid == 0) chunk_base = 0;
    for (int start = 0; start < N_NODES; start += 1024) {
        __syncthreads();
        int i = start + tid;
        int v = (i < N_NODES) ? g_icnt[i] : 0;
        int x = v;
#pragma unroll
        for (int d = 1; d < 32; d <<= 1) {
            int y = __shfl_up_sync(0xffffffffu, x, d);
            if (lane >= d) x += y;
        }
        if (lane == 31) wsum[wid] = x;
        __syncthreads();
        if (wid == 0) {
            int s = wsum[lane];
#pragma unroll
            for (int d = 1; d < 32; d <<= 1) {
                int y = __shfl_up_sync(0xffffffffu, s, d);
                if (lane >= d) s += y;
            }
            wsum[lane] = s;
        }
        __syncthreads();
        int wbase = (wid > 0) ? wsum[wid - 1] : 0;
        if (i < N_NODES) g_off[i] = chunk_base + wbase + x - v;
        __syncthreads();
        if (tid == 0) chunk_base += wsum[31];
    }
    __syncthreads();
    if (threadIdx.x == 0) g_off[N_NODES] = chunk_base;
}

__global__ void k_fill(const int* __restrict__ edge_index) {
    int e = blockIdx.x * blockDim.x + threadIdx.x;
    if (e >= N_EDGES) return;
    int c = edge_index[N_EDGES + e];
    int pos = g_off[c] + atomicAdd(&g_icnt[N_NODES + c], 1);
    g_csr[pos] = edge_index[e];  // source node
}

// ---------------- edge_attr aggregation (once) ----------------
__global__ void k_edge_aggr(const float* __restrict__ edge_attr,
                            const int* __restrict__ edge_index,
                            float* __restrict__ out) {
    int tid = blockIdx.x * blockDim.x + threadIdx.x;
    int e = tid >> 3, p = tid & 7;
    if (e >= N_EDGES) return;
    int r = edge_index[e];
    float4 v = *reinterpret_cast<const float4*>(edge_attr + (size_t)e * EC + p * 4);
    red4(out + (size_t)r * EC + p * 4, v);
}

// ---------------- CSR gather: agg[n] = sum_{e: col=n} y[row(e)] ----------------
__global__ void k_gather() {
    int tid = threadIdx.x;
    int node = blockIdx.x * 16 + (tid >> 4);
    int p = tid & 15;
    if (node >= N_NODES) return;
    int s = g_off[node], e = g_off[node + 1];
    float4 a0 = make_float4(0.f, 0.f, 0.f, 0.f);
    float4 a1 = make_float4(0.f, 0.f, 0.f, 0.f);
    int i = s;
    for (; i + 1 < e; i += 2) {
        int s0 = g_csr[i], s1 = g_csr[i + 1];
        float4 v0 = *reinterpret_cast<const float4*>(&g_y[(size_t)s0 * H_CH + p * 4]);
        float4 v1 = *reinterpret_cast<const float4*>(&g_y[(size_t)s1 * H_CH + p * 4]);
        a0.x += v0.x; a0.y += v0.y; a0.z += v0.z; a0.w += v0.w;
        a1.x += v1.x; a1.y += v1.y; a1.z += v1.z; a1.w += v1.w;
    }
    if (i < e) {
        int s0 = g_csr[i];
        float4 v0 = *reinterpret_cast<const float4*>(&g_y[(size_t)s0 * H_CH + p * 4]);
        a0.x += v0.x; a0.y += v0.y; a0.z += v0.z; a0.w += v0.w;
    }
    float4 r = make_float4(a0.x + a1.x, a0.y + a1.y, a0.z + a1.z, a0.w + a1.w);
    *reinterpret_cast<float4*>(&g_agg[(size_t)node * H_CH + p * 4]) = r;
}

// ---------------- node MLP stage 1 (FFMA2) ----------------
// y = xc @ W1_rel (raw);  u = relu(xc @ W1_root + b1_root);  xc = [x_in | edge_aggr]
__global__ void k_node_mlp1(const float* __restrict__ x_in,
                            const float* __restrict__ W1_rel,
                            const float* __restrict__ W1_root,
                            const float* __restrict__ b1_root) {
    extern __shared__ float sm[];
    float* xs = sm;            // [64][100]
    float* Ws = sm + 6400;     // [96][128]  [W1_rel | W1_root]
    float* b1 = Ws + 12288;    // [64]
    const int tid = threadIdx.x;
    const int node0 = blockIdx.x * 64;

    for (int i = tid; i < 96 * 128; i += 256) {
        int k = i >> 7, j = i & 127;
        Ws[i] = (j < 64) ? W1_rel[k * 64 + j] : W1_root[k * 64 + (j - 64)];
    }
    if (tid < 64) b1[tid] = b1_root[tid];
    for (int i = tid; i < 64 * 96; i += 256) {
        int n = i / 96, k = i - n * 96;
        int node = node0 + n;
        float v = 0.f;
        if (node < N_NODES)
            v = (k < 64) ? x_in[(size_t)node * 64 + k]
                         : g_edge_aggr[(size_t)node * EC + (k - 64)];
        xs[n * 100 + k] = v;
    }
    __syncthreads();

    const int og = tid & 15, ng = tid >> 4;
    const int j0 = og * 8;
    unsigned long long acc[4][4];
#pragma unroll
    for (int i = 0; i < 4; i++)
#pragma unroll
        for (int j = 0; j < 4; j++) acc[i][j] = 0ull;

#pragma unroll 4
    for (int k = 0; k < 96; k++) {
        ulonglong2 wA = *reinterpret_cast<const ulonglong2*>(&Ws[k * 128 + j0]);
        ulonglong2 wB = *reinterpret_cast<const ulonglong2*>(&Ws[k * 128 + j0 + 4]);
#pragma unroll
        for (int i = 0; i < 4; i++) {
            unsigned long long aa = bcast2(xs[(ng + 16 * i) * 100 + k]);
            ffma2(acc[i][0], aa, wA.x);
            ffma2(acc[i][1], aa, wA.y);
            ffma2(acc[i][2], aa, wB.x);
            ffma2(acc[i][3], aa, wB.y);
        }
    }

#pragma unroll
    for (int i = 0; i < 4; i++) {
        int node = node0 + ng + 16 * i;
        if (node >= N_NODES) continue;
        float2 f0 = u2f(acc[i][0]), f1 = u2f(acc[i][1]);
        float2 f2 = u2f(acc[i][2]), f3 = u2f(acc[i][3]);
        if (og < 8) {
            float4 o0 = make_float4(f0.x, f0.y, f1.x, f1.y);
            float4 o1 = make_float4(f2.x, f2.y, f3.x, f3.y);
            *reinterpret_cast<float4*>(&g_y[(size_t)node * 64 + j0]) = o0;
            *reinterpret_cast<float4*>(&g_y[(size_t)node * 64 + j0 + 4]) = o1;
        } else {
            int jr = j0 - 64;
            float4 o0 = make_float4(fmaxf(f0.x + b1[jr + 0], 0.f),
                                    fmaxf(f0.y + b1[jr + 1], 0.f),
                                    fmaxf(f1.x + b1[jr + 2], 0.f),
                                    fmaxf(f1.y + b1[jr + 3], 0.f));
            float4 o1 = make_float4(fmaxf(f2.x + b1[jr + 4], 0.f),
                                    fmaxf(f2.y + b1[jr + 5], 0.f),
                                    fmaxf(f3.x + b1[jr + 6], 0.f),
                                    fmaxf(f3.y + b1[jr + 7], 0.f));
            *reinterpret_cast<float4*>(&g_u[(size_t)node * 64 + jr]) = o0;
            *reinterpret_cast<float4*>(&g_u[(size_t)node * 64 + jr + 4]) = o1;
        }
    }
}

// ---------------- node MLP stage 2 (FFMA2) + optional fused pooling ----------------
// x_out = relu([relu(agg + b1_rel) | u] @ [W2_rel ; W2_root] + b2_rel + b2_root)
__global__ void k_node_mlp2(const float* __restrict__ b1_rel,
                            const float* __restrict__ W2_rel,
                            const float* __restrict__ W2_root,
                            const float* __restrict__ b2_rel,
                            const float* __restrict__ b2_root,
                            const int* __restrict__ batch,
                            int final_layer) {
    extern __shared__ float sm[];
    float* As = sm;            // [64][132]
    float* Ws = sm + 8448;     // [128][64]
    float* b2 = Ws + 8192;     // [64]
    const int tid = threadIdx.x;
    const int node0 = blockIdx.x * 64;

    for (int i = tid; i < 128 * 64; i += 256) {
        int k = i >> 6, j = i & 63;
        Ws[i] = (k < 64) ? W2_rel[k * 64 + j] : W2_root[(k - 64) * 64 + j];
    }
    if (tid < 64) b2[tid] = b2_rel[tid] + b2_root[tid];
    for (int i = tid; i < 64 * 128; i += 256) {
        int n = i >> 7, k = i & 127;
        int node = node0 + n;
        float v = 0.f;
        if (node < N_NODES) {
            if (k < 64) v = fmaxf(g_agg[(size_t)node * 64 + k] + b1_rel[k], 0.f);
            else        v = g_u[(size_t)node * 64 + (k - 64)];
        }
        As[n * 132 + k] = v;
    }
    __syncthreads();

    const int og = tid & 15, ng = tid >> 4;
    const int j0 = og * 4;
    unsigned long long acc[4][2];
#pragma unroll
    for (int i = 0; i < 4; i++) { acc[i][0] = 0ull; acc[i][1] = 0ull; }

#pragma unroll 4
    for (int k = 0; k < 128; k++) {
        ulonglong2 w = *reinterpret_cast<const ulonglong2*>(&Ws[k * 64 + j0]);
#pragma unroll
        for (int i = 0; i < 4; i++) {
            unsigned long long aa = bcast2(As[(ng + 16 * i) * 132 + k]);
            ffma2(acc[i][0], aa, w.x);
            ffma2(acc[i][1], aa, w.y);
        }
    }

#pragma unroll
    for (int i = 0; i < 4; i++) {
        int node = node0 + ng + 16 * i;
        if (node >= N_NODES) continue;
        float2 f0 = u2f(acc[i][0]), f1 = u2f(acc[i][1]);
        float4 o = make_float4(fmaxf(f0.x + b2[j0 + 0], 0.f),
                               fmaxf(f0.y + b2[j0 + 1], 0.f),
                               fmaxf(f1.x + b2[j0 + 2], 0.f),
                               fmaxf(f1.y + b2[j0 + 3], 0.f));
        if (final_layer) {
            int b = batch[node];
            red4(&g_pooled[(size_t)b * 64 + j0], o);
        } else {
            *reinterpret_cast<float4*>(&g_x[(size_t)node * 64 + j0]) = o;
        }
    }
}

// ---------------- final MLP ----------------
__global__ void k_final(const float* __restrict__ W1, const float* __restrict__ b1,
                        const float* __restrict__ W2, const float* __restrict__ b2,
                        float* __restrict__ out) {
    __shared__ float pr[64];
    __shared__ float h[64];
    int g = blockIdx.x;
    int j = threadIdx.x;
    pr[j] = g_pooled[g * 64 + j];
    __syncthreads();
    float s = b1[j];
#pragma unroll 8
    for (int k = 0; k < 64; k++) s = fmaf(pr[k], W1[k * 64 + j], s);
    h[j] = fmaxf(s, 0.f);
    __syncthreads();
    if (j < OUT_CH) {
        float s2 = b2[j];
#pragma unroll 8
        for (int k = 0; k < 64; k++) s2 = fmaf(h[k], W2[k * OUT_CH + j], s2);
        out[g * OUT_CH + j] = s2;
    }
}

// ---------------- launch ----------------
extern "C" void kernel_launch(void* const* d_in, const int* in_sizes, int n_in,
                              void* d_out, int out_size) {
    const float* x         = (const float*)d_in[0];
    const float* edge_attr = (const float*)d_in[1];
    const float* relW1[2]  = {(const float*)d_in[2],  (const float*)d_in[10]};
    const float* relb1[2]  = {(const float*)d_in[3],  (const float*)d_in[11]};
    const float* relW2[2]  = {(const float*)d_in[4],  (const float*)d_in[12]};
    const float* relb2[2]  = {(const float*)d_in[5],  (const float*)d_in[13]};
    const float* rootW1[2] = {(const float*)d_in[6],  (const float*)d_in[14]};
    const float* rootb1[2] = {(const float*)d_in[7],  (const float*)d_in[15]};
    const float* rootW2[2] = {(const float*)d_in[8],  (const float*)d_in[16]};
    const float* rootb2[2] = {(const float*)d_in[9],  (const float*)d_in[17]};
    const float* finW1 = (const float*)d_in[18];
    const float* finb1 = (const float*)d_in[19];
    const float* finW2 = (const float*)d_in[20];
    const float* finb2 = (const float*)d_in[21];
    const int* edge_index = (const int*)d_in[22];
    const int* batch      = (const int*)d_in[23];
    float* out = (float*)d_out;

    float *p_ea, *p_x, *p_pooled;
    int *p_icnt;
    cudaGetSymbolAddress((void**)&p_ea, g_edge_aggr);
    cudaGetSymbolAddress((void**)&p_x, g_x);
    cudaGetSymbolAddress((void**)&p_pooled, g_pooled);
    cudaGetSymbolAddress((void**)&p_icnt, g_icnt);

    const int SMEM1 = (6400 + 12288 + 64) * 4;
    const int SMEM2 = (8448 + 8192 + 64) * 4;
    cudaFuncSetAttribute(k_node_mlp1, cudaFuncAttributeMaxDynamicSharedMemorySize, SMEM1);
    cudaFuncSetAttribute(k_node_mlp2, cudaFuncAttributeMaxDynamicSharedMemorySize, SMEM2);

    const int NODE_BLOCKS = (N_NODES + 63) / 64;   // 782
    const int EDGE_BLOCKS = (N_EDGES + 255) / 256; // 6250

    // zeroing (graph-capturable memset nodes)
    cudaMemsetAsync(p_icnt, 0, 2 * N_NODES * sizeof(int), 0);
    cudaMemsetAsync(p_ea, 0, N_NODES * EC * sizeof(float), 0);
    cudaMemsetAsync(p_pooled, 0, G_GRAPHS * H_CH * sizeof(float), 0);

    // CSR by target (col)
    k_hist<<<EDGE_BLOCKS, 256>>>(edge_index);
    k_scan<<<1, 1024>>>();
    k_fill<<<EDGE_BLOCKS, 256>>>(edge_index);

    // layer-invariant edge_attr aggregation
    k_edge_aggr<<<(N_EDGES * 8) / 256, 256>>>(edge_attr, edge_index, p_ea);

    for (int l = 0; l < 2; l++) {
        const float* x_in = (l == 0) ? x : p_x;
        k_node_mlp1<<<NODE_BLOCKS, 256, SMEM1>>>(x_in, relW1[l], rootW1[l], rootb1[l]);
        k_gather<<<(N_NODES + 15) / 16, 256>>>();
        k_node_mlp2<<<NODE_BLOCKS, 256, SMEM2>>>(relb1[l], relW2[l], rootW2[l],
                                                 relb2[l], rootb2[l], batch, l == 1);
    }

    k_final<<<G_GRAPHS, 64>>>(finW1, finb1, finW2, finb2, out);
}

// round 3
// speedup vs baseline: 1.2448x; 1.1046x over previous
#include <cuda_runtime.h>
#include <cstdint>

#define N_NODES 50000
#define N_EDGES 1600000
#define G_GRAPHS 256
#define IN_CH 64
#define EC 32
#define H_CH 64
#define OUT_CH 10

// ---------------- scratch ----------------
__device__ float g_edge_aggr[N_NODES * EC];
__device__ float g_y[N_NODES * H_CH];
__device__ float g_u[N_NODES * H_CH];
__device__ float g_agg[N_NODES * H_CH];
__device__ float g_x[N_NODES * H_CH];
__device__ float g_pooled[G_GRAPHS * H_CH];
__device__ int   g_icnt[2 * N_NODES];   // [0..N): hist counts, [N..2N): fill cursors
__device__ int   g_off[N_NODES + 1];
__device__ int   g_csr[N_EDGES];

// ---------------- PTX helpers ----------------
__device__ __forceinline__ void red4(float* addr, float4 v) {
    asm volatile("red.global.add.v4.f32 [%0], {%1,%2,%3,%4};"
                 :: "l"(addr), "f"(v.x), "f"(v.y), "f"(v.z), "f"(v.w)
                 : "memory");
}
__device__ __forceinline__ void ffma2(unsigned long long& d,
                                      unsigned long long a, unsigned long long b) {
    asm("fma.rn.f32x2 %0, %1, %2, %0;" : "+l"(d) : "l"(a), "l"(b));
}
__device__ __forceinline__ unsigned long long bcast2(float a) {
    unsigned long long r;
    asm("mov.b64 %0, {%1, %1};" : "=l"(r) : "f"(a));
    return r;
}
__device__ __forceinline__ float2 u2f(unsigned long long v) {
    float2 f;
    asm("mov.b64 {%0, %1}, %2;" : "=f"(f.x), "=f"(f.y) : "l"(v));
    return f;
}

// ---------------- CSR build ----------------
__global__ void k_hist(const int* __restrict__ edge_index) {
    int e = blockIdx.x * blockDim.x + threadIdx.x;
    if (e >= N_EDGES) return;
    atomicAdd(&g_icnt[edge_index[N_EDGES + e]], 1);
}

__global__ void k_scan() {
    __shared__ int wsum[32];
    __shared__ int chunk_base;
    int tid = threadIdx.x, lane = tid & 31, wid = tid >> 5;
    if (tid == 0) chunk_base = 0;
    for (int start = 0; start < N_NODES; start += 4096) {
        __syncthreads();
        int idx = start + tid * 4;
        int a0 = 0, a1 = 0, a2 = 0, a3 = 0;
        if (idx + 3 < N_NODES) {
            int4 t = *reinterpret_cast<const int4*>(&g_icnt[idx]);
            a0 = t.x; a1 = t.y; a2 = t.z; a3 = t.w;
        } else if (idx < N_NODES) {
            a0 = g_icnt[idx];
            if (idx + 1 < N_NODES) a1 = g_icnt[idx + 1];
            if (idx + 2 < N_NODES) a2 = g_icnt[idx + 2];
        }
        int v = a0 + a1 + a2 + a3;
        int x = v;
#pragma unroll
        for (int d = 1; d < 32; d <<= 1) {
            int y = __shfl_up_sync(0xffffffffu, x, d);
            if (lane >= d) x += y;
        }
        if (lane == 31) wsum[wid] = x;
        __syncthreads();
        if (wid == 0) {
            int s = wsum[lane];
#pragma unroll
            for (int d = 1; d < 32; d <<= 1) {
                int y = __shfl_up_sync(0xffffffffu, s, d);
                if (lane >= d) s += y;
            }
            wsum[lane] = s;
        }
        __syncthreads();
        int wbase = (wid > 0) ? wsum[wid - 1] : 0;
        int base = chunk_base + wbase + x - v;
        if (idx < N_NODES)     g_off[idx]     = base;
        if (idx + 1 < N_NODES) g_off[idx + 1] = base + a0;
        if (idx + 2 < N_NODES) g_off[idx + 2] = base + a0 + a1;
        if (idx + 3 < N_NODES) g_off[idx + 3] = base + a0 + a1 + a2;
        __syncthreads();
        if (tid == 0) chunk_base += wsum[31];
    }
    __syncthreads();
    if (tid == 0) g_off[N_NODES] = chunk_base;
}

__global__ void k_fill(const int* __restrict__ edge_index) {
    int e = blockIdx.x * blockDim.x + threadIdx.x;
    if (e >= N_EDGES) return;
    int c = edge_index[N_EDGES + e];
    int pos = g_off[c] + atomicAdd(&g_icnt[N_NODES + c], 1);
    g_csr[pos] = edge_index[e];  // source node
}

// ---------------- edge_attr aggregation (once): 2 edges per thread ----------------
__global__ void k_edge_aggr(const float* __restrict__ edge_attr,
                            const int* __restrict__ edge_index,
                            float* __restrict__ out) {
    const int HALF = N_EDGES / 2;
    int tid = blockIdx.x * blockDim.x + threadIdx.x;
    int e = tid >> 3, p4 = (tid & 7) * 4;
    if (e >= HALF) return;
    int e2 = e + HALF;
    int r0 = edge_index[e];
    int r1 = edge_index[e2];
    float4 v0 = *reinterpret_cast<const float4*>(edge_attr + (size_t)e  * EC + p4);
    float4 v1 = *reinterpret_cast<const float4*>(edge_attr + (size_t)e2 * EC + p4);
    red4(out + (size_t)r0 * EC + p4, v0);
    red4(out + (size_t)r1 * EC + p4, v1);
}

// ---------------- CSR gather: agg[n] = sum_{e: col=n} y[row(e)], unroll 4 ----------------
__global__ void k_gather() {
    int tid = threadIdx.x;
    int node = blockIdx.x * 16 + (tid >> 4);
    int p4 = (tid & 15) * 4;
    if (node >= N_NODES) return;
    int s = g_off[node], e = g_off[node + 1];
    float4 a0 = make_float4(0.f, 0.f, 0.f, 0.f);
    float4 a1 = a0, a2 = a0, a3 = a0;
    int i = s;
    for (; i + 4 <= e; i += 4) {
        int n0 = g_csr[i], n1 = g_csr[i + 1], n2 = g_csr[i + 2], n3 = g_csr[i + 3];
        float4 v0 = *reinterpret_cast<const float4*>(&g_y[(size_t)n0 * H_CH + p4]);
        float4 v1 = *reinterpret_cast<const float4*>(&g_y[(size_t)n1 * H_CH + p4]);
        float4 v2 = *reinterpret_cast<const float4*>(&g_y[(size_t)n2 * H_CH + p4]);
        float4 v3 = *reinterpret_cast<const float4*>(&g_y[(size_t)n3 * H_CH + p4]);
        a0.x += v0.x; a0.y += v0.y; a0.z += v0.z; a0.w += v0.w;
        a1.x += v1.x; a1.y += v1.y; a1.z += v1.z; a1.w += v1.w;
        a2.x += v2.x; a2.y += v2.y; a2.z += v2.z; a2.w += v2.w;
        a3.x += v3.x; a3.y += v3.y; a3.z += v3.z; a3.w += v3.w;
    }
    for (; i < e; i++) {
        int n0 = g_csr[i];
        float4 v0 = *reinterpret_cast<const float4*>(&g_y[(size_t)n0 * H_CH + p4]);
        a0.x += v0.x; a0.y += v0.y; a0.z += v0.z; a0.w += v0.w;
    }
    float4 r = make_float4(a0.x + a1.x + a2.x + a3.x,
                           a0.y + a1.y + a2.y + a3.y,
                           a0.z + a1.z + a2.z + a3.z,
                           a0.w + a1.w + a2.w + a3.w);
    *reinterpret_cast<float4*>(&g_agg[(size_t)node * H_CH + p4]) = r;
}

// ---------------- node MLP stage 1 (FFMA2) ----------------
__global__ void k_node_mlp1(const float* __restrict__ x_in,
                            const float* __restrict__ W1_rel,
                            const float* __restrict__ W1_root,
                            const float* __restrict__ b1_root) {
    extern __shared__ float sm[];
    float* xs = sm;            // [64][100]
    float* Ws = sm + 6400;     // [96][128]  [W1_rel | W1_root]
    float* b1 = Ws + 12288;    // [64]
    const int tid = threadIdx.x;
    const int node0 = blockIdx.x * 64;

    for (int i = tid; i < 96 * 128; i += 256) {
        int k = i >> 7, j = i & 127;
        Ws[i] = (j < 64) ? W1_rel[k * 64 + j] : W1_root[k * 64 + (j - 64)];
    }
    if (tid < 64) b1[tid] = b1_root[tid];
    for (int i = tid; i < 64 * 96; i += 256) {
        int n = i / 96, k = i - n * 96;
        int node = node0 + n;
        float v = 0.f;
        if (node < N_NODES)
            v = (k < 64) ? x_in[(size_t)node * 64 + k]
                         : g_edge_aggr[(size_t)node * EC + (k - 64)];
        xs[n * 100 + k] = v;
    }
    __syncthreads();

    const int og = tid & 15, ng = tid >> 4;
    const int j0 = og * 8;
    unsigned long long acc[4][4];
#pragma unroll
    for (int i = 0; i < 4; i++)
#pragma unroll
        for (int j = 0; j < 4; j++) acc[i][j] = 0ull;

#pragma unroll 4
    for (int k = 0; k < 96; k++) {
        ulonglong2 wA = *reinterpret_cast<const ulonglong2*>(&Ws[k * 128 + j0]);
        ulonglong2 wB = *reinterpret_cast<const ulonglong2*>(&Ws[k * 128 + j0 + 4]);
#pragma unroll
        for (int i = 0; i < 4; i++) {
            unsigned long long aa = bcast2(xs[(ng + 16 * i) * 100 + k]);
            ffma2(acc[i][0], aa, wA.x);
            ffma2(acc[i][1], aa, wA.y);
            ffma2(acc[i][2], aa, wB.x);
            ffma2(acc[i][3], aa, wB.y);
        }
    }

#pragma unroll
    for (int i = 0; i < 4; i++) {
        int node = node0 + ng + 16 * i;
        if (node >= N_NODES) continue;
        float2 f0 = u2f(acc[i][0]), f1 = u2f(acc[i][1]);
        float2 f2 = u2f(acc[i][2]), f3 = u2f(acc[i][3]);
        if (og < 8) {
            float4 o0 = make_float4(f0.x, f0.y, f1.x, f1.y);
            float4 o1 = make_float4(f2.x, f2.y, f3.x, f3.y);
            *reinterpret_cast<float4*>(&g_y[(size_t)node * 64 + j0]) = o0;
            *reinterpret_cast<float4*>(&g_y[(size_t)node * 64 + j0 + 4]) = o1;
        } else {
            int jr = j0 - 64;
            float4 o0 = make_float4(fmaxf(f0.x + b1[jr + 0], 0.f),
                                    fmaxf(f0.y + b1[jr + 1], 0.f),
                                    fmaxf(f1.x + b1[jr + 2], 0.f),
                                    fmaxf(f1.y + b1[jr + 3], 0.f));
            float4 o1 = make_float4(fmaxf(f2.x + b1[jr + 4], 0.f),
                                    fmaxf(f2.y + b1[jr + 5], 0.f),
                                    fmaxf(f3.x + b1[jr + 6], 0.f),
                                    fmaxf(f3.y + b1[jr + 7], 0.f));
            *reinterpret_cast<float4*>(&g_u[(size_t)node * 64 + jr]) = o0;
            *reinterpret_cast<float4*>(&g_u[(size_t)node * 64 + jr + 4]) = o1;
        }
    }
}

// ---------------- node MLP stage 2 (FFMA2) + fused pooling on last layer ----------------
__global__ void k_node_mlp2(const float* __restrict__ b1_rel,
                            const float* __restrict__ W2_rel,
                            const float* __restrict__ W2_root,
                            const float* __restrict__ b2_rel,
                            const float* __restrict__ b2_root,
                            const int* __restrict__ batch,
                            int final_layer) {
    extern __shared__ float sm[];
    float* As = sm;            // [64][132]
    float* Ws = sm + 8448;     // [128][64]
    float* b2 = Ws + 8192;     // [64]
    const int tid = threadIdx.x;
    const int node0 = blockIdx.x * 64;

    for (int i = tid; i < 128 * 64; i += 256) {
        int k = i >> 6, j = i & 63;
        Ws[i] = (k < 64) ? W2_rel[k * 64 + j] : W2_root[(k - 64) * 64 + j];
    }
    if (tid < 64) b2[tid] = b2_rel[tid] + b2_root[tid];
    for (int i = tid; i < 64 * 128; i += 256) {
        int n = i >> 7, k = i & 127;
        int node = node0 + n;
        float v = 0.f;
        if (node < N_NODES) {
            if (k < 64) v = fmaxf(g_agg[(size_t)node * 64 + k] + b1_rel[k], 0.f);
            else        v = g_u[(size_t)node * 64 + (k - 64)];
        }
        As[n * 132 + k] = v;
    }
    __syncthreads();

    const int og = tid & 15, ng = tid >> 4;
    const int j0 = og * 4;
    unsigned long long acc[4][2];
#pragma unroll
    for (int i = 0; i < 4; i++) { acc[i][0] = 0ull; acc[i][1] = 0ull; }

#pragma unroll 4
    for (int k = 0; k < 128; k++) {
        ulonglong2 w = *reinterpret_cast<const ulonglong2*>(&Ws[k * 64 + j0]);
#pragma unroll
        for (int i = 0; i < 4; i++) {
            unsigned long long aa = bcast2(As[(ng + 16 * i) * 132 + k]);
            ffma2(acc[i][0], aa, w.x);
            ffma2(acc[i][1], aa, w.y);
        }
    }

#pragma unroll
    for (int i = 0; i < 4; i++) {
        int node = node0 + ng + 16 * i;
        if (node >= N_NODES) continue;
        float2 f0 = u2f(acc[i][0]), f1 = u2f(acc[i][1]);
        float4 o = make_float4(fmaxf(f0.x + b2[j0 + 0], 0.f),
                               fmaxf(f0.y + b2[j0 + 1], 0.f),
                               fmaxf(f1.x + b2[j0 + 2], 0.f),
                               fmaxf(f1.y + b2[j0 + 3], 0.f));
        if (final_layer) {
            int b = batch[node];
            red4(&g_pooled[(size_t)b * 64 + j0], o);
        } else {
            *reinterpret_cast<float4*>(&g_x[(size_t)node * 64 + j0]) = o;
        }
    }
}

// ---------------- final MLP ----------------
__global__ void k_final(const float* __restrict__ W1, const float* __restrict__ b1,
                        const float* __restrict__ W2, const float* __restrict__ b2,
                        float* __restrict__ out) {
    __shared__ float pr[64];
    __shared__ float h[64];
    int g = blockIdx.x;
    int j = threadIdx.x;
    pr[j] = g_pooled[g * 64 + j];
    __syncthreads();
    float s = b1[j];
#pragma unroll 8
    for (int k = 0; k < 64; k++) s = fmaf(pr[k], W1[k * 64 + j], s);
    h[j] = fmaxf(s, 0.f);
    __syncthreads();
    if (j < OUT_CH) {
        float s2 = b2[j];
#pragma unroll 8
        for (int k = 0; k < 64; k++) s2 = fmaf(h[k], W2[k * OUT_CH + j], s2);
        out[g * OUT_CH + j] = s2;
    }
}

// ---------------- launch ----------------
extern "C" void kernel_launch(void* const* d_in, const int* in_sizes, int n_in,
                              void* d_out, int out_size) {
    const float* x         = (const float*)d_in[0];
    const float* edge_attr = (const float*)d_in[1];
    const float* relW1[2]  = {(const float*)d_in[2],  (const float*)d_in[10]};
    const float* relb1[2]  = {(const float*)d_in[3],  (const float*)d_in[11]};
    const float* relW2[2]  = {(const float*)d_in[4],  (const float*)d_in[12]};
    const float* relb2[2]  = {(const float*)d_in[5],  (const float*)d_in[13]};
    const float* rootW1[2] = {(const float*)d_in[6],  (const float*)d_in[14]};
    const float* rootb1[2] = {(const float*)d_in[7],  (const float*)d_in[15]};
    const float* rootW2[2] = {(const float*)d_in[8],  (const float*)d_in[16]};
    const float* rootb2[2] = {(const float*)d_in[9],  (const float*)d_in[17]};
    const float* finW1 = (const float*)d_in[18];
    const float* finb1 = (const float*)d_in[19];
    const float* finW2 = (const float*)d_in[20];
    const float* finb2 = (const float*)d_in[21];
    const int* edge_index = (const int*)d_in[22];
    const int* batch      = (const int*)d_in[23];
    float* out = (float*)d_out;

    float *p_ea, *p_x, *p_pooled;
    int *p_icnt;
    cudaGetSymbolAddress((void**)&p_ea, g_edge_aggr);
    cudaGetSymbolAddress((void**)&p_x, g_x);
    cudaGetSymbolAddress((void**)&p_pooled, g_pooled);
    cudaGetSymbolAddress((void**)&p_icnt, g_icnt);

    const int SMEM1 = (6400 + 12288 + 64) * 4;
    const int SMEM2 = (8448 + 8192 + 64) * 4;
    cudaFuncSetAttribute(k_node_mlp1, cudaFuncAttributeMaxDynamicSharedMemorySize, SMEM1);
    cudaFuncSetAttribute(k_node_mlp2, cudaFuncAttributeMaxDynamicSharedMemorySize, SMEM2);

    // one-time resources (no device memory involved)
    static cudaStream_t s2 = nullptr;
    static cudaEvent_t evF = nullptr, evJ = nullptr;
    if (!s2) {
        cudaStreamCreateWithFlags(&s2, cudaStreamNonBlocking);
        cudaEventCreateWithFlags(&evF, cudaEventDisableTiming);
        cudaEventCreateWithFlags(&evJ, cudaEventDisableTiming);
    }

    const int NODE_BLOCKS = (N_NODES + 63) / 64;   // 782
    const int EDGE_BLOCKS = (N_EDGES + 255) / 256; // 6250

    // ---- fork: CSR build on side stream (only needed by k_gather) ----
    cudaEventRecord(evF, 0);
    cudaStreamWaitEvent(s2, evF, 0);
    cudaMemsetAsync(p_icnt, 0, 2 * N_NODES * sizeof(int), s2);
    k_hist<<<EDGE_BLOCKS, 256, 0, s2>>>(edge_index);
    k_scan<<<1, 1024, 0, s2>>>();
    k_fill<<<EDGE_BLOCKS, 256, 0, s2>>>(edge_index);
    cudaEventRecord(evJ, s2);

    // ---- main stream: edge_attr aggregation + layer-0 mlp1 overlap CSR build ----
    cudaMemsetAsync(p_ea, 0, N_NODES * EC * sizeof(float), 0);
    cudaMemsetAsync(p_pooled, 0, G_GRAPHS * H_CH * sizeof(float), 0);
    k_edge_aggr<<<(N_EDGES / 2 * 8) / 256, 256>>>(edge_attr, edge_index, p_ea);

    k_node_mlp1<<<NODE_BLOCKS, 256, SMEM1>>>(x, relW1[0], rootW1[0], rootb1[0]);
    cudaStreamWaitEvent(0, evJ, 0);  // join before first gather
    k_gather<<<(N_NODES + 15) / 16, 256>>>();
    k_node_mlp2<<<NODE_BLOCKS, 256, SMEM2>>>(relb1[0], relW2[0], rootW2[0],
                                             relb2[0], rootb2[0], batch, 0);

    k_node_mlp1<<<NODE_BLOCKS, 256, SMEM1>>>(p_x, relW1[1], rootW1[1], rootb1[1]);
    k_gather<<<(N_NODES + 15) / 16, 256>>>();
    k_node_mlp2<<<NODE_BLOCKS, 256, SMEM2>>>(relb1[1], relW2[1], rootW2[1],
                                             relb2[1], rootb2[1], batch, 1);

    k_final<<<G_GRAPHS, 64>>>(finW1, finb1, finW2, finb2, out);
}

// round 4
// speedup vs baseline: 1.2721x; 1.0219x over previous
#include <cuda_runtime.h>
#include <cuda_fp16.h>
#include <cstdint>

#define N_NODES 50000
#define N_EDGES 1600000
#define G_GRAPHS 256
#define IN_CH 64
#define EC 32
#define H_CH 64
#define OUT_CH 10

// ---------------- scratch ----------------
__device__ float  g_edge_aggr[N_NODES * EC];
__device__ __half g_y[N_NODES * H_CH];        // fp16: halves gather traffic
__device__ float  g_u[N_NODES * H_CH];
__device__ float  g_agg[N_NODES * H_CH];
__device__ float  g_x[N_NODES * H_CH];
__device__ float  g_pooled[G_GRAPHS * H_CH];
__device__ int    g_icnt[2 * N_NODES];
__device__ int    g_off[N_NODES + 1];
__device__ int    g_csr[N_EDGES];

// ---------------- PTX helpers ----------------
__device__ __forceinline__ void red4(float* addr, float4 v) {
    asm volatile("red.global.add.v4.f32 [%0], {%1,%2,%3,%4};"
                 :: "l"(addr), "f"(v.x), "f"(v.y), "f"(v.z), "f"(v.w)
                 : "memory");
}
__device__ __forceinline__ void ffma2(unsigned long long& d,
                                      unsigned long long a, unsigned long long b) {
    asm("fma.rn.f32x2 %0, %1, %2, %0;" : "+l"(d) : "l"(a), "l"(b));
}
__device__ __forceinline__ unsigned long long bcast2(float a) {
    unsigned long long r;
    asm("mov.b64 %0, {%1, %1};" : "=l"(r) : "f"(a));
    return r;
}
__device__ __forceinline__ float2 u2f(unsigned long long v) {
    float2 f;
    asm("mov.b64 {%0, %1}, %2;" : "=f"(f.x), "=f"(f.y) : "l"(v));
    return f;
}

// ---------------- CSR build ----------------
__global__ void k_hist(const int* __restrict__ edge_index) {
    int e = blockIdx.x * blockDim.x + threadIdx.x;
    if (e >= N_EDGES) return;
    atomicAdd(&g_icnt[edge_index[N_EDGES + e]], 1);
}

__global__ void k_scan() {
    __shared__ int wsum[32];
    __shared__ int chunk_base;
    int tid = threadIdx.x, lane = tid & 31, wid = tid >> 5;
    if (tid == 0) chunk_base = 0;
    for (int start = 0; start < N_NODES; start += 4096) {
        __syncthreads();
        int idx = start + tid * 4;
        int a0 = 0, a1 = 0, a2 = 0, a3 = 0;
        if (idx + 3 < N_NODES) {
            int4 t = *reinterpret_cast<const int4*>(&g_icnt[idx]);
            a0 = t.x; a1 = t.y; a2 = t.z; a3 = t.w;
        } else if (idx < N_NODES) {
            a0 = g_icnt[idx];
            if (idx + 1 < N_NODES) a1 = g_icnt[idx + 1];
            if (idx + 2 < N_NODES) a2 = g_icnt[idx + 2];
        }
        int v = a0 + a1 + a2 + a3;
        int x = v;
#pragma unroll
        for (int d = 1; d < 32; d <<= 1) {
            int y = __shfl_up_sync(0xffffffffu, x, d);
            if (lane >= d) x += y;
        }
        if (lane == 31) wsum[wid] = x;
        __syncthreads();
        if (wid == 0) {
            int s = wsum[lane];
#pragma unroll
            for (int d = 1; d < 32; d <<= 1) {
                int y = __shfl_up_sync(0xffffffffu, s, d);
                if (lane >= d) s += y;
            }
            wsum[lane] = s;
        }
        __syncthreads();
        int wbase = (wid > 0) ? wsum[wid - 1] : 0;
        int base = chunk_base + wbase + x - v;
        if (idx < N_NODES)     g_off[idx]     = base;
        if (idx + 1 < N_NODES) g_off[idx + 1] = base + a0;
        if (idx + 2 < N_NODES) g_off[idx + 2] = base + a0 + a1;
        if (idx + 3 < N_NODES) g_off[idx + 3] = base + a0 + a1 + a2;
        __syncthreads();
        if (tid == 0) chunk_base += wsum[31];
    }
    __syncthreads();
    if (tid == 0) g_off[N_NODES] = chunk_base;
}

__global__ void k_fill(const int* __restrict__ edge_index) {
    int e = blockIdx.x * blockDim.x + threadIdx.x;
    if (e >= N_EDGES) return;
    int c = edge_index[N_EDGES + e];
    int pos = g_off[c] + atomicAdd(&g_icnt[N_NODES + c], 1);
    g_csr[pos] = edge_index[e];
}

// ---------------- edge_attr aggregation: 4 edges/thread, loads front-batched ----------------
__global__ void k_edge_aggr(const float* __restrict__ edge_attr,
                            const int* __restrict__ edge_index,
                            float* __restrict__ out) {
    const int Q = N_EDGES / 4;
    int tid = blockIdx.x * blockDim.x + threadIdx.x;
    int e = tid >> 3, p4 = (tid & 7) * 4;
    if (e >= Q) return;
    int e1 = e + Q, e2 = e + 2 * Q, e3 = e + 3 * Q;
    int r0 = edge_index[e],  r1 = edge_index[e1];
    int r2 = edge_index[e2], r3 = edge_index[e3];
    float4 v0 = *reinterpret_cast<const float4*>(edge_attr + (size_t)e  * EC + p4);
    float4 v1 = *reinterpret_cast<const float4*>(edge_attr + (size_t)e1 * EC + p4);
    float4 v2 = *reinterpret_cast<const float4*>(edge_attr + (size_t)e2 * EC + p4);
    float4 v3 = *reinterpret_cast<const float4*>(edge_attr + (size_t)e3 * EC + p4);
    red4(out + (size_t)r0 * EC + p4, v0);
    red4(out + (size_t)r1 * EC + p4, v1);
    red4(out + (size_t)r2 * EC + p4, v2);
    red4(out + (size_t)r3 * EC + p4, v3);
}

// ---------------- CSR gather (fp16 payload): agg[n] = sum y[src], unroll 4 ----------------
__global__ void k_gather() {
    int tid = threadIdx.x;
    int node = blockIdx.x * 32 + (tid >> 3);
    int p8 = (tid & 7) * 8;              // 8 halves = 16B per thread
    if (node >= N_NODES) return;
    int s = g_off[node], e = g_off[node + 1];
    float acc0[8], acc1[8];
#pragma unroll
    for (int j = 0; j < 8; j++) { acc0[j] = 0.f; acc1[j] = 0.f; }

    int i = s;
    for (; i + 4 <= e; i += 4) {
        int n0 = g_csr[i], n1 = g_csr[i + 1], n2 = g_csr[i + 2], n3 = g_csr[i + 3];
        uint4 v0 = *reinterpret_cast<const uint4*>(&g_y[(size_t)n0 * H_CH + p8]);
        uint4 v1 = *reinterpret_cast<const uint4*>(&g_y[(size_t)n1 * H_CH + p8]);
        uint4 v2 = *reinterpret_cast<const uint4*>(&g_y[(size_t)n2 * H_CH + p8]);
        uint4 v3 = *reinterpret_cast<const uint4*>(&g_y[(size_t)n3 * H_CH + p8]);
        const __half2* h0 = reinterpret_cast<const __half2*>(&v0);
        const __half2* h1 = reinterpret_cast<const __half2*>(&v1);
        const __half2* h2 = reinterpret_cast<const __half2*>(&v2);
        const __half2* h3 = reinterpret_cast<const __half2*>(&v3);
#pragma unroll
        for (int q = 0; q < 4; q++) {
            float2 f0 = __half22float2(h0[q]);
            float2 f1 = __half22float2(h1[q]);
            float2 f2 = __half22float2(h2[q]);
            float2 f3 = __half22float2(h3[q]);
            acc0[q * 2]     += f0.x + f2.x;
            acc0[q * 2 + 1] += f0.y + f2.y;
            acc1[q * 2]     += f1.x + f3.x;
            acc1[q * 2 + 1] += f1.y + f3.y;
        }
    }
    for (; i < e; i++) {
        int n0 = g_csr[i];
        uint4 v0 = *reinterpret_cast<const uint4*>(&g_y[(size_t)n0 * H_CH + p8]);
        const __half2* h0 = reinterpret_cast<const __half2*>(&v0);
#pragma unroll
        for (int q = 0; q < 4; q++) {
            float2 f0 = __half22float2(h0[q]);
            acc0[q * 2]     += f0.x;
            acc0[q * 2 + 1] += f0.y;
        }
    }
    float4 o0 = make_float4(acc0[0] + acc1[0], acc0[1] + acc1[1],
                            acc0[2] + acc1[2], acc0[3] + acc1[3]);
    float4 o1 = make_float4(acc0[4] + acc1[4], acc0[5] + acc1[5],
                            acc0[6] + acc1[6], acc0[7] + acc1[7]);
    *reinterpret_cast<float4*>(&g_agg[(size_t)node * H_CH + p8])     = o0;
    *reinterpret_cast<float4*>(&g_agg[(size_t)node * H_CH + p8 + 4]) = o1;
}

// ---------------- node MLP stage 1 (FFMA2); y stored fp16 ----------------
__global__ void k_node_mlp1(const float* __restrict__ x_in,
                            const float* __restrict__ W1_rel,
                            const float* __restrict__ W1_root,
                            const float* __restrict__ b1_root) {
    extern __shared__ float sm[];
    float* xs = sm;            // [64][100]
    float* Ws = sm + 6400;     // [96][128]
    float* b1 = Ws + 12288;    // [64]
    const int tid = threadIdx.x;
    const int node0 = blockIdx.x * 64;

    for (int i = tid; i < 96 * 128; i += 256) {
        int k = i >> 7, j = i & 127;
        Ws[i] = (j < 64) ? W1_rel[k * 64 + j] : W1_root[k * 64 + (j - 64)];
    }
    if (tid < 64) b1[tid] = b1_root[tid];
    for (int i = tid; i < 64 * 96; i += 256) {
        int n = i / 96, k = i - n * 96;
        int node = node0 + n;
        float v = 0.f;
        if (node < N_NODES)
            v = (k < 64) ? x_in[(size_t)node * 64 + k]
                         : g_edge_aggr[(size_t)node * EC + (k - 64)];
        xs[n * 100 + k] = v;
    }
    __syncthreads();

    const int og = tid & 15, ng = tid >> 4;
    const int j0 = og * 8;
    unsigned long long acc[4][4];
#pragma unroll
    for (int i = 0; i < 4; i++)
#pragma unroll
        for (int j = 0; j < 4; j++) acc[i][j] = 0ull;

#pragma unroll 4
    for (int k = 0; k < 96; k++) {
        ulonglong2 wA = *reinterpret_cast<const ulonglong2*>(&Ws[k * 128 + j0]);
        ulonglong2 wB = *reinterpret_cast<const ulonglong2*>(&Ws[k * 128 + j0 + 4]);
#pragma unroll
        for (int i = 0; i < 4; i++) {
            unsigned long long aa = bcast2(xs[(ng + 16 * i) * 100 + k]);
            ffma2(acc[i][0], aa, wA.x);
            ffma2(acc[i][1], aa, wA.y);
            ffma2(acc[i][2], aa, wB.x);
            ffma2(acc[i][3], aa, wB.y);
        }
    }

#pragma unroll
    for (int i = 0; i < 4; i++) {
        int node = node0 + ng + 16 * i;
        if (node >= N_NODES) continue;
        float2 f0 = u2f(acc[i][0]), f1 = u2f(acc[i][1]);
        float2 f2 = u2f(acc[i][2]), f3 = u2f(acc[i][3]);
        if (og < 8) {
            // pack 8 floats -> 8 halves (16B)
            __half2 h0 = __floats2half2_rn(f0.x, f0.y);
            __half2 h1 = __floats2half2_rn(f1.x, f1.y);
            __half2 h2 = __floats2half2_rn(f2.x, f2.y);
            __half2 h3 = __floats2half2_rn(f3.x, f3.y);
            uint4 pk;
            pk.x = *reinterpret_cast<unsigned int*>(&h0);
            pk.y = *reinterpret_cast<unsigned int*>(&h1);
            pk.z = *reinterpret_cast<unsigned int*>(&h2);
            pk.w = *reinterpret_cast<unsigned int*>(&h3);
            *reinterpret_cast<uint4*>(&g_y[(size_t)node * 64 + j0]) = pk;
        } else {
            int jr = j0 - 64;
            float4 o0 = make_float4(fmaxf(f0.x + b1[jr + 0], 0.f),
                                    fmaxf(f0.y + b1[jr + 1], 0.f),
                                    fmaxf(f1.x + b1[jr + 2], 0.f),
                                    fmaxf(f1.y + b1[jr + 3], 0.f));
            float4 o1 = make_float4(fmaxf(f2.x + b1[jr + 4], 0.f),
                                    fmaxf(f2.y + b1[jr + 5], 0.f),
                                    fmaxf(f3.x + b1[jr + 6], 0.f),
                                    fmaxf(f3.y + b1[jr + 7], 0.f));
            *reinterpret_cast<float4*>(&g_u[(size_t)node * 64 + jr]) = o0;
            *reinterpret_cast<float4*>(&g_u[(size_t)node * 64 + jr + 4]) = o1;
        }
    }
}

// ---------------- node MLP stage 2 (FFMA2) + fused pooling on last layer ----------------
__global__ void k_node_mlp2(const float* __restrict__ b1_rel,
                            const float* __restrict__ W2_rel,
                            const float* __restrict__ W2_root,
                            const float* __restrict__ b2_rel,
                            const float* __restrict__ b2_root,
                            const int* __restrict__ batch,
                            int final_layer) {
    extern __shared__ float sm[];
    float* As = sm;            // [64][132]
    float* Ws = sm + 8448;     // [128][64]
    float* b2 = Ws + 8192;     // [64]
    const int tid = threadIdx.x;
    const int node0 = blockIdx.x * 64;

    for (int i = tid; i < 128 * 64; i += 256) {
        int k = i >> 6, j = i & 63;
        Ws[i] = (k < 64) ? W2_rel[k * 64 + j] : W2_root[(k - 64) * 64 + j];
    }
    if (tid < 64) b2[tid] = b2_rel[tid] + b2_root[tid];
    for (int i = tid; i < 64 * 128; i += 256) {
        int n = i >> 7, k = i & 127;
        int node = node0 + n;
        float v = 0.f;
        if (node < N_NODES) {
            if (k < 64) v = fmaxf(g_agg[(size_t)node * 64 + k] + b1_rel[k], 0.f);
            else        v = g_u[(size_t)node * 64 + (k - 64)];
        }
        As[n * 132 + k] = v;
    }
    __syncthreads();

    const int og = tid & 15, ng = tid >> 4;
    const int j0 = og * 4;
    unsigned long long acc[4][2];
#pragma unroll
    for (int i = 0; i < 4; i++) { acc[i][0] = 0ull; acc[i][1] = 0ull; }

#pragma unroll 4
    for (int k = 0; k < 128; k++) {
        ulonglong2 w = *reinterpret_cast<const ulonglong2*>(&Ws[k * 64 + j0]);
#pragma unroll
        for (int i = 0; i < 4; i++) {
            unsigned long long aa = bcast2(As[(ng + 16 * i) * 132 + k]);
            ffma2(acc[i][0], aa, w.x);
            ffma2(acc[i][1], aa, w.y);
        }
    }

#pragma unroll
    for (int i = 0; i < 4; i++) {
        int node = node0 + ng + 16 * i;
        if (node >= N_NODES) continue;
        float2 f0 = u2f(acc[i][0]), f1 = u2f(acc[i][1]);
        float4 o = make_float4(fmaxf(f0.x + b2[j0 + 0], 0.f),
                               fmaxf(f0.y + b2[j0 + 1], 0.f),
                               fmaxf(f1.x + b2[j0 + 2], 0.f),
                               fmaxf(f1.y + b2[j0 + 3], 0.f));
        if (final_layer) {
            int b = batch[node];
            red4(&g_pooled[(size_t)b * 64 + j0], o);
        } else {
            *reinterpret_cast<float4*>(&g_x[(size_t)node * 64 + j0]) = o;
        }
    }
}

// ---------------- final MLP ----------------
__global__ void k_final(const float* __restrict__ W1, const float* __restrict__ b1,
                        const float* __restrict__ W2, const float* __restrict__ b2,
                        float* __restrict__ out) {
    __shared__ float pr[64];
    __shared__ float h[64];
    int g = blockIdx.x;
    int j = threadIdx.x;
    pr[j] = g_pooled[g * 64 + j];
    __syncthreads();
    float s = b1[j];
#pragma unroll 8
    for (int k = 0; k < 64; k++) s = fmaf(pr[k], W1[k * 64 + j], s);
    h[j] = fmaxf(s, 0.f);
    __syncthreads();
    if (j < OUT_CH) {
        float s2 = b2[j];
#pragma unroll 8
        for (int k = 0; k < 64; k++) s2 = fmaf(h[k], W2[k * OUT_CH + j], s2);
        out[g * OUT_CH + j] = s2;
    }
}

// ---------------- launch ----------------
extern "C" void kernel_launch(void* const* d_in, const int* in_sizes, int n_in,
                              void* d_out, int out_size) {
    const float* x         = (const float*)d_in[0];
    const float* edge_attr = (const float*)d_in[1];
    const float* relW1[2]  = {(const float*)d_in[2],  (const float*)d_in[10]};
    const float* relb1[2]  = {(const float*)d_in[3],  (const float*)d_in[11]};
    const float* relW2[2]  = {(const float*)d_in[4],  (const float*)d_in[12]};
    const float* relb2[2]  = {(const float*)d_in[5],  (const float*)d_in[13]};
    const float* rootW1[2] = {(const float*)d_in[6],  (const float*)d_in[14]};
    const float* rootb1[2] = {(const float*)d_in[7],  (const float*)d_in[15]};
    const float* rootW2[2] = {(const float*)d_in[8],  (const float*)d_in[16]};
    const float* rootb2[2] = {(const float*)d_in[9],  (const float*)d_in[17]};
    const float* finW1 = (const float*)d_in[18];
    const float* finb1 = (const float*)d_in[19];
    const float* finW2 = (const float*)d_in[20];
    const float* finb2 = (const float*)d_in[21];
    const int* edge_index = (const int*)d_in[22];
    const int* batch      = (const int*)d_in[23];
    float* out = (float*)d_out;

    float *p_ea, *p_x, *p_pooled;
    int *p_icnt;
    cudaGetSymbolAddress((void**)&p_ea, g_edge_aggr);
    cudaGetSymbolAddress((void**)&p_x, g_x);
    cudaGetSymbolAddress((void**)&p_pooled, g_pooled);
    cudaGetSymbolAddress((void**)&p_icnt, g_icnt);

    const int SMEM1 = (6400 + 12288 + 64) * 4;
    const int SMEM2 = (8448 + 8192 + 64) * 4;
    cudaFuncSetAttribute(k_node_mlp1, cudaFuncAttributeMaxDynamicSharedMemorySize, SMEM1);
    cudaFuncSetAttribute(k_node_mlp2, cudaFuncAttributeMaxDynamicSharedMemorySize, SMEM2);

    static cudaStream_t s2 = nullptr;
    static cudaEvent_t evF = nullptr, evJ = nullptr;
    if (!s2) {
        cudaStreamCreateWithFlags(&s2, cudaStreamNonBlocking);
        cudaEventCreateWithFlags(&evF, cudaEventDisableTiming);
        cudaEventCreateWithFlags(&evJ, cudaEventDisableTiming);
    }

    const int NODE_BLOCKS = (N_NODES + 63) / 64;
    const int EDGE_BLOCKS = (N_EDGES + 255) / 256;

    // ---- fork: CSR build on side stream ----
    cudaEventRecord(evF, 0);
    cudaStreamWaitEvent(s2, evF, 0);
    cudaMemsetAsync(p_icnt, 0, 2 * N_NODES * sizeof(int), s2);
    k_hist<<<EDGE_BLOCKS, 256, 0, s2>>>(edge_index);
    k_scan<<<1, 1024, 0, s2>>>();
    k_fill<<<EDGE_BLOCKS, 256, 0, s2>>>(edge_index);
    cudaEventRecord(evJ, s2);

    // ---- main stream ----
    cudaMemsetAsync(p_ea, 0, N_NODES * EC * sizeof(float), 0);
    cudaMemsetAsync(p_pooled, 0, G_GRAPHS * H_CH * sizeof(float), 0);
    k_edge_aggr<<<(N_EDGES / 4 * 8 + 255) / 256, 256>>>(edge_attr, edge_index, p_ea);

    k_node_mlp1<<<NODE_BLOCKS, 256, SMEM1>>>(x, relW1[0], rootW1[0], rootb1[0]);
    cudaStreamWaitEvent(0, evJ, 0);
    k_gather<<<(N_NODES + 31) / 32, 256>>>();
    k_node_mlp2<<<NODE_BLOCKS, 256, SMEM2>>>(relb1[0], relW2[0], rootW2[0],
                                             relb2[0], rootb2[0], batch, 0);

    k_node_mlp1<<<NODE_BLOCKS, 256, SMEM1>>>(p_x, relW1[1], rootW1[1], rootb1[1]);
    k_gather<<<(N_NODES + 31) / 32, 256>>>();
    k_node_mlp2<<<NODE_BLOCKS, 256, SMEM2>>>(relb1[1], relW2[1], rootW2[1],
                                             relb2[1], rootb2[1], batch, 1);

    k_final<<<G_GRAPHS, 64>>>(finW1, finb1, finW2, finb2, out);
}